// round 11
// baseline (speedup 1.0000x reference)
#include <cuda_runtime.h>
#include <cuda_bf16.h>
#include <cuda_fp16.h>
#include <cstdint>

#define LROW 8192
#define NROWS 256
#define OUT_TILE 249
#define NTILES 33   // 33*249 = 8217 >= 8192
#define HROWS 260

// ---------------- device globals ----------------
// conv2 B-fragments, per-thread kb-contiguous: [nb][lane][kb][2]
static __device__ __align__(16) uint32_t g_w2f[8 * 32 * 10 * 2];
// conv3 B-fragments: [lane][kb][2]
static __device__ __align__(16) uint32_t g_w3f[32 * 10 * 2];
static __device__ float    g_stat[NROWS * 2];

// ---------------- smem layout (bytes) ----------------
// H rows: 260 x 80B (64 e4m3 + 16B pad; stride 80 => conflict-free ldmatrix)
// scoef/sg/sf OVERLAY the H region (only live after all sH reads are done).
#define OFF_H    0                    // 20800
#define OFF_COEF OFF_H                // 256 x float4 = 4096 (overlay)
#define OFF_G    (OFF_H + 4096)      // 1024 (overlay)
#define OFF_F    (OFF_H + 5120)      // 1024 (overlay)
#define OFF_W2F  20800                // 20480
#define OFF_W3F  (OFF_W2F + 20480)   // 41280: 2560
#define OFF_PRIM (OFF_W3F + 2560)    // 43840: 264 f32 -> 1072 (pad)
#define OFF_Y    (OFF_PRIM + 1072)   // 44912: 264 f32 -> 1072 (pad)
#define OFF_B2   (OFF_Y + 1072)      // 45984: 256
#define OFF_B3   (OFF_B2 + 256)      // 46240: 32
#define SMEM_TOTAL (OFF_B3 + 32)     // 46272 (x5 = 231.4 KB/SM)

// ---------------- helpers ----------------
__device__ __forceinline__ uint32_t smem_u32(const void* p) {
    uint32_t a;
    asm("{ .reg .u64 t; cvta.to.shared.u64 t, %1; cvt.u32.u64 %0, t; }" : "=r"(a) : "l"(p));
    return a;
}
__device__ __forceinline__ void sts16(uint32_t a, unsigned short v) {
    asm volatile("st.shared.b16 [%0], %1;" :: "r"(a), "h"(v) : "memory");
}
__device__ __forceinline__ void ldmatrix_x4(uint32_t* r, uint32_t a) {
    asm volatile("ldmatrix.sync.aligned.m8n8.x4.shared.b16 {%0,%1,%2,%3}, [%4];"
                 : "=r"(r[0]), "=r"(r[1]), "=r"(r[2]), "=r"(r[3]) : "r"(a));
}
__device__ __forceinline__ void mma_fp8_h(uint32_t* d, const uint32_t* a, uint32_t b0, uint32_t b1) {
    asm volatile("mma.sync.aligned.m16n8k32.row.col.f16.e4m3.e4m3.f16 "
                 "{%0,%1}, {%2,%3,%4,%5}, {%6,%7}, {%0,%1};"
                 : "+r"(d[0]), "+r"(d[1])
                 : "r"(a[0]), "r"(a[1]), "r"(a[2]), "r"(a[3]), "r"(b0), "r"(b1));
}
__device__ __forceinline__ unsigned short tanh_h2_e4m3(uint32_t h) {
    asm("tanh.approx.f16x2 %0, %0;" : "+r"(h));
    unsigned short e;
    asm("cvt.rn.satfinite.e4m3x2.f16x2 %0, %1;" : "=h"(e) : "r"(h));
    return e;
}
__device__ __forceinline__ uint32_t packh2(float lo, float hi) {
    uint32_t h;
    asm("cvt.rn.f16x2.f32 %0, %1, %2;" : "=r"(h) : "f"(hi), "f"(lo));
    return h;
}
__device__ __forceinline__ uint32_t pack4_e4m3(float v0, float v1, float v2, float v3) {
    unsigned short lo, hi;
    asm("cvt.rn.satfinite.e4m3x2.f32 %0, %1, %2;" : "=h"(lo) : "f"(v1), "f"(v0));
    asm("cvt.rn.satfinite.e4m3x2.f32 %0, %1, %2;" : "=h"(hi) : "f"(v3), "f"(v2));
    uint32_t r;
    asm("mov.b32 %0, {%1,%2};" : "=r"(r) : "h"(lo), "h"(hi));
    return r;
}

// ---------------- K0 merged: blocks<256 row stats; blocks>=256 weight packing ----------------
__global__ void k_pre(const float* __restrict__ prim,
                      const float* __restrict__ W2, const float* __restrict__ W3) {
    int tid = threadIdx.x;
    if (blockIdx.x < 256) {
        int row = blockIdx.x;
        const float4* p4 = reinterpret_cast<const float4*>(prim + (size_t)row * LROW);
        float mn = 3.4e38f, mx = -3.4e38f;
        for (int i = tid; i < LROW / 4; i += 256) {
            float4 v = p4[i];
            mn = fminf(mn, fminf(fminf(v.x, v.y), fminf(v.z, v.w)));
            mx = fmaxf(mx, fmaxf(fmaxf(v.x, v.y), fmaxf(v.z, v.w)));
        }
        for (int o = 16; o; o >>= 1) {
            mn = fminf(mn, __shfl_xor_sync(0xffffffffu, mn, o));
            mx = fmaxf(mx, __shfl_xor_sync(0xffffffffu, mx, o));
        }
        __shared__ float smn[8], smx[8];
        if ((tid & 31) == 0) { smn[tid >> 5] = mn; smx[tid >> 5] = mx; }
        __syncthreads();
        if (tid == 0) {
            for (int w = 1; w < 8; w++) { mn = fminf(mn, smn[w]); mx = fmaxf(mx, smx[w]); }
            g_stat[2 * row]     = mn;
            g_stat[2 * row + 1] = 1.0f / fmaxf((mx - mn) * 0.5f, 1e-4f);
        }
    } else {
        int base = (blockIdx.x - 256) * 256 + tid;
        int nth = 24 * 256;
        // layout: j = (((nb*32)+lane)*10 + kb)*2 + r
        for (int j = base; j < 8 * 32 * 10 * 2; j += nth) {
            int r = j & 1;
            int t = j >> 1;
            int kb = t % 10;
            int t2 = t / 10;
            int lane = t2 & 31, nb = t2 >> 5;
            int tg = lane & 3, gg = lane >> 2;
            int kshift = kb >> 1;
            int ci = (kb & 1) * 32 + r * 16 + tg * 4;
            int co = nb * 8 + gg;
            const float* wb = W2 + kshift * 4096 + ci * 64 + co;
            g_w2f[j] = pack4_e4m3(wb[0], wb[64], wb[128], wb[192]);
        }
        // layout: j = (lane*10 + kb)*2 + r
        for (int j = base; j < 32 * 10 * 2; j += nth) {
            int r = j & 1;
            int t = j >> 1;
            int kb = t % 10;
            int lane = t / 10;
            int tg = lane & 3, gg = lane >> 2;
            int kshift = kb >> 1;
            int ci = (kb & 1) * 32 + r * 16 + tg * 4;
            float v0 = 0, v1 = 0, v2 = 0, v3 = 0;
            if (gg < 4) {
                const float* wb = W3 + kshift * 256 + ci * 4 + gg;
                v0 = wb[0]; v1 = wb[4]; v2 = wb[8]; v3 = wb[12];
            }
            g_w3f[j] = pack4_e4m3(v0, v1, v2, v3);
        }
    }
}

// ---------------- mega kernel ----------------
__global__ void __launch_bounds__(256, 5)
k_mega(const float* __restrict__ prim,
       const float* __restrict__ W1g, const float* __restrict__ b1g,
       const float* __restrict__ b2g, const float* __restrict__ b3g,
       float* __restrict__ out) {
    extern __shared__ __align__(16) char smem[];
    int tid = threadIdx.x;
    int w = tid >> 5, lane = tid & 31;
    int tg = lane & 3, gg = lane >> 2;
    int row = blockIdx.y;
    int t0 = blockIdx.x * OUT_TILE;
    size_t rb = (size_t)row * LROW;

    uint32_t sh_base = smem_u32(smem) + OFF_H;
    float* sPrim = reinterpret_cast<float*>(smem + OFF_PRIM);
    float* sy    = reinterpret_cast<float*>(smem + OFF_Y);
    float* sb2   = reinterpret_cast<float*>(smem + OFF_B2);
    float* sb3   = reinterpret_cast<float*>(smem + OFF_B3);
    float* scoef = reinterpret_cast<float*>(smem + OFF_COEF);   // overlays sH
    float* sg    = reinterpret_cast<float*>(smem + OFF_G);      // overlays sH
    float* sf    = reinterpret_cast<float*>(smem + OFF_F);      // overlays sH

    // ---- phase 0: stage weights (smem) + prim + rescale ----
    {
        uint4* d2 = reinterpret_cast<uint4*>(smem + OFF_W2F);
        const uint4* s2 = reinterpret_cast<const uint4*>(g_w2f);
        for (int i = tid; i < 1280; i += 256) d2[i] = s2[i];
        uint4* d3 = reinterpret_cast<uint4*>(smem + OFF_W3F);
        const uint4* s3 = reinterpret_cast<const uint4*>(g_w3f);
        for (int i = tid; i < 160; i += 256) d3[i] = s3[i];
        float mn = g_stat[2 * row], inv = g_stat[2 * row + 1];
        for (int j = tid; j < 264; j += 256) {
            float p = prim[rb + ((t0 - 8 + j) & (LROW - 1))];
            sPrim[j] = p;
            sy[j] = (p - mn) * inv - 1.0f;
        }
        if (tid < 64) sb2[tid] = b2g[tid];
        if (tid < 4)  sb3[tid] = b3g[tid];
    }
    // conv1 weights into registers (global loads; lane = channel pair)
    __half2 hw[5], hbr;
    {
        float2 bv = *reinterpret_cast<const float2*>(b1g + 2 * lane);
        uint32_t u = packh2(bv.x, bv.y);
        hbr = *reinterpret_cast<__half2*>(&u);
#pragma unroll
        for (int k = 0; k < 5; k++) {
            float2 wv = *reinterpret_cast<const float2*>(W1g + k * 64 + 2 * lane);
            uint32_t uu = packh2(wv.x, wv.y);
            hw[k] = *reinterpret_cast<__half2*>(&uu);
        }
    }
    __syncthreads();

    // ---- phase 1: conv1 (half2, weights in regs, sliding window) -> sH1 ----
    {
        int j0 = w * 33;
        int jend = j0 + 33 < HROWS ? j0 + 33 : HROWS;
        __half2 hy[5];
#pragma unroll
        for (int i = 0; i < 5; i++) hy[i] = __float2half2_rn(sy[j0 + i]);
        for (int j = j0; j < jend; j++) {
            __half2 a = hbr;
            a = __hfma2(hy[0], hw[0], a);
            a = __hfma2(hy[1], hw[1], a);
            a = __hfma2(hy[2], hw[2], a);
            a = __hfma2(hy[3], hw[3], a);
            a = __hfma2(hy[4], hw[4], a);
            sts16(sh_base + j * 80 + lane * 2,
                  tanh_h2_e4m3(*reinterpret_cast<uint32_t*>(&a)));
            hy[0] = hy[1]; hy[1] = hy[2]; hy[2] = hy[3]; hy[3] = hy[4];
            hy[4] = __float2half2_rn(sy[j + 5]);
        }
    }
    __syncthreads();

    // ---- phase 2+3: conv2 fp8 MMA in two N-halves (acc 16 regs each), tanh -> regs ----
    int m0 = w * 32;
    uint32_t aBase = sh_base + (uint32_t)((m0 + (lane & 15)) * 80 + ((lane >> 4) << 4));

    unsigned short h2e[2][4][2][2];   // [half][nb0][mt][r]
#pragma unroll
    for (int half = 0; half < 2; half++) {
        uint32_t acc[4][2][2];        // [nb0][mt][r]
#pragma unroll
        for (int nb0 = 0; nb0 < 4; nb0++) {
            int c0 = (half * 4 + nb0) * 8 + tg * 2;
            uint32_t binit = packh2(sb2[c0], sb2[c0 + 1]);
#pragma unroll
            for (int mt = 0; mt < 2; mt++) { acc[nb0][mt][0] = binit; acc[nb0][mt][1] = binit; }
        }
#pragma unroll
        for (int kbp = 0; kbp < 5; kbp++) {
            uint32_t ae[2][4], ao[2][4];
#pragma unroll
            for (int mt = 0; mt < 2; mt++) {
                uint32_t ad = aBase + (uint32_t)(mt * 1280 + kbp * 80);
                ldmatrix_x4(ae[mt], ad);
                ldmatrix_x4(ao[mt], ad + 32);
            }
#pragma unroll
            for (int nb0 = 0; nb0 < 4; nb0++) {
                int nb = half * 4 + nb0;
                uint4 b = *reinterpret_cast<const uint4*>(
                    smem + OFF_W2F + (size_t)((nb * 32 + lane) * 5 + kbp) * 16);
                mma_fp8_h(acc[nb0][0], ae[0], b.x, b.y);
                mma_fp8_h(acc[nb0][1], ae[1], b.x, b.y);
                mma_fp8_h(acc[nb0][0], ao[0], b.z, b.w);
                mma_fp8_h(acc[nb0][1], ao[1], b.z, b.w);
            }
        }
#pragma unroll
        for (int nb0 = 0; nb0 < 4; nb0++)
#pragma unroll
            for (int mt = 0; mt < 2; mt++) {
                h2e[half][nb0][mt][0] = tanh_h2_e4m3(acc[nb0][mt][0]);
                h2e[half][nb0][mt][1] = tanh_h2_e4m3(acc[nb0][mt][1]);
            }
    }
    __syncthreads();   // all warps done reading sH1
#pragma unroll
    for (int half = 0; half < 2; half++)
#pragma unroll
        for (int mt = 0; mt < 2; mt++) {
            uint32_t r0 = (uint32_t)(m0 + mt * 16 + gg);
#pragma unroll
            for (int nb0 = 0; nb0 < 4; nb0++) {
                uint32_t cb = (uint32_t)((half * 4 + nb0) * 8 + tg * 2);
                sts16(sh_base + r0 * 80 + cb, h2e[half][nb0][mt][0]);
                sts16(sh_base + (r0 + 8) * 80 + cb, h2e[half][nb0][mt][1]);
            }
        }
    __syncthreads();

    // ---- phase 4: conv3 fp8 MMA, f16 accum (M=256, N=8pad, K=320) -> coeffs ----
    uint32_t acc3[2][2];
    {
        uint32_t bz = (tg < 2) ? packh2(sb3[tg * 2], sb3[tg * 2 + 1]) : 0u;
#pragma unroll
        for (int mt = 0; mt < 2; mt++) { acc3[mt][0] = bz; acc3[mt][1] = bz; }
    }
#pragma unroll
    for (int kbp = 0; kbp < 5; kbp++) {
        uint32_t ae[2][4], ao[2][4];
#pragma unroll
        for (int mt = 0; mt < 2; mt++) {
            uint32_t ad = aBase + (uint32_t)(mt * 1280 + kbp * 80);
            ldmatrix_x4(ae[mt], ad);
            ldmatrix_x4(ao[mt], ad + 32);
        }
        uint4 b = *reinterpret_cast<const uint4*>(
            smem + OFF_W3F + (size_t)(lane * 5 + kbp) * 16);
        mma_fp8_h(acc3[0], ae[0], b.x, b.y);
        mma_fp8_h(acc3[1], ae[1], b.x, b.y);
        mma_fp8_h(acc3[0], ao[0], b.z, b.w);
        mma_fp8_h(acc3[1], ao[1], b.z, b.w);
    }
    __syncthreads();   // sH reads done before scoef overlays it
    if (tg < 2) {
#pragma unroll
        for (int mt = 0; mt < 2; mt++) {
            int p = m0 + mt * 16 + gg;
            int c0 = tg * 2;
            float2 v01 = __half22float2(*reinterpret_cast<__half2*>(&acc3[mt][0]));
            float2 v23 = __half22float2(*reinterpret_cast<__half2*>(&acc3[mt][1]));
            scoef[p * 4 + c0]           = v01.x;
            scoef[p * 4 + c0 + 1]       = v01.y;
            scoef[(p + 8) * 4 + c0]     = v23.x;
            scoef[(p + 8) * 4 + c0 + 1] = v23.y;
        }
    }
    __syncthreads();

    // ---- phase 5: alpha -> grad -> TVD flux -> update ----
    if (tid < 252) {   // grad at position t0-2+tid
        float4 c = *reinterpret_cast<const float4*>(scoef + tid * 4);
        float S = c.x + c.y + c.z + c.w;
        const float NB0 = -0.44721359549995793f;
        const float NBD = -0.13819660112501052f;
        float a0 = (float)( 1.0 / 12.0) + NB0 * S;
        float a1 = (float)(-2.0 / 3.0)  + c.x + NBD * S;
        float a2 =                        c.y + NBD * S;
        float a3 = (float)( 2.0 / 3.0)  + c.z + NBD * S;
        float a4 = (float)(-1.0 / 12.0) + c.w + NBD * S;
        float g = sPrim[tid + 4] * a0 + sPrim[tid + 5] * a1 + sPrim[tid + 6] * a2
                + sPrim[tid + 7] * a3 + sPrim[tid + 8] * a4;
        sg[tid] = g * 64.0f;
    }
    __syncthreads();
    if (tid < 250) {   // flux at position t0-1+tid
        float gm1 = sg[tid], g0 = sg[tid + 1], g1 = sg[tid + 2];
        float aa0 = (g0 < 0.0f) ? -1.0f : 1.0f;
        float ri0 = gm1 / (fmaxf(fabsf(g0), 1e-15f) * aa0);
        float phi0 = (ri0 * ri0 + ri0) / (ri0 * ri0 + 1.0f);
        float aa1 = (g1 < 0.0f) ? -1.0f : 1.0f;
        float ri1 = g0 / (fmaxf(fabsf(g1), 1e-15f) * aa1);
        float phi1 = (ri1 * ri1 + ri1) / (ri1 * ri1 + 1.0f);
        float uL = sPrim[tid + 7] + 0.0078125f * phi0 * g0;
        float uR = sPrim[tid + 8] - 0.0078125f * phi1 * g1;
        sf[tid] = 0.25f * (uL * uL + uR * uR) - 0.25f * fabsf(uL + uR) * (uR - uL);
    }
    __syncthreads();
    if (tid < OUT_TILE) {
        int o = t0 + tid;
        if (o < LROW)
            out[rb + o] = sPrim[tid + 8] - 0.01f * (sf[tid + 1] - sf[tid]);
    }
}

// ---------------- launch ----------------
extern "C" void kernel_launch(void* const* d_in, const int* in_sizes, int n_in,
                              void* d_out, int out_size) {
    const float* Prim = (const float*)d_in[0];
    const float* W1   = (const float*)d_in[1];
    const float* b1   = (const float*)d_in[2];
    const float* W2   = (const float*)d_in[3];
    const float* b2   = (const float*)d_in[4];
    const float* W3   = (const float*)d_in[5];
    const float* b3   = (const float*)d_in[6];
    float* out = (float*)d_out;

    cudaFuncSetAttribute(k_mega, cudaFuncAttributeMaxDynamicSharedMemorySize, SMEM_TOTAL);

    k_pre<<<280, 256>>>(Prim, W2, W3);
    k_mega<<<dim3(NTILES, NROWS), 256, SMEM_TOTAL>>>(Prim, W1, b1, b2, b3, out);
}

// round 13
// speedup vs baseline: 3.6452x; 3.6452x over previous
#include <cuda_runtime.h>
#include <cuda_bf16.h>
#include <cuda_fp16.h>
#include <cstdint>

#define LROW 8192
#define NROWS 256
#define OUT_TILE 249
#define NTILES 33   // 33*249 = 8217 >= 8192
#define HROWS 260

// ---------------- device globals ----------------
static __device__ __align__(16) uint32_t g_w2f[10 * 8 * 32 * 2];  // conv2 e4m3 B-frags [kb][nb][lane][2]
static __device__ __align__(16) uint32_t g_w3f[10 * 32 * 2];      // conv3 e4m3 B-frags [kb][lane][2]
static __device__ float    g_stat[NROWS * 2];

// ---------------- smem layout (bytes) ----------------
// H rows: 260 x 80B (64 e4m3 + 16B pad; stride 80 => conflict-free ldmatrix)
#define OFF_H    0                    // 20800
#define OFF_W2F  20800                // 20480
#define OFF_W3F  (OFF_W2F + 20480)   // 41280: 2560
#define OFF_PRIM (OFF_W3F + 2560)    // 43840: 264 f32 -> 1056
#define OFF_Y    (OFF_PRIM + 1056)   // 44896: 264 f32 -> 1056
#define OFF_B2   (OFF_Y + 1056)      // 45952: 256
#define OFF_B3   (OFF_B2 + 256)      // 46208: 32
#define OFF_COEF (OFF_B3 + 32)       // 46240: 256 x float4 -> 4096
#define OFF_G    (OFF_COEF + 4096)   // 50336: 1024
#define OFF_F    (OFF_G + 1024)      // 51360: 1024
#define SMEM_TOTAL (OFF_F + 1024)    // 52384 (x4 = 209.5 KB/SM)

// ---------------- helpers ----------------
__device__ __forceinline__ uint32_t smem_u32(const void* p) {
    uint32_t a;
    asm("{ .reg .u64 t; cvta.to.shared.u64 t, %1; cvt.u32.u64 %0, t; }" : "=r"(a) : "l"(p));
    return a;
}
__device__ __forceinline__ void sts16(uint32_t a, unsigned short v) {
    asm volatile("st.shared.b16 [%0], %1;" :: "r"(a), "h"(v) : "memory");
}
__device__ __forceinline__ void cp_async16(uint32_t dst, const void* src) {
    asm volatile("cp.async.cg.shared.global [%0], [%1], 16;" :: "r"(dst), "l"(src) : "memory");
}
__device__ __forceinline__ void ldmatrix_x4(uint32_t* r, uint32_t a) {
    asm volatile("ldmatrix.sync.aligned.m8n8.x4.shared.b16 {%0,%1,%2,%3}, [%4];"
                 : "=r"(r[0]), "=r"(r[1]), "=r"(r[2]), "=r"(r[3]) : "r"(a));
}
__device__ __forceinline__ void mma_fp8_h(uint32_t* d, const uint32_t* a, uint32_t b0, uint32_t b1) {
    asm volatile("mma.sync.aligned.m16n8k32.row.col.f16.e4m3.e4m3.f16 "
                 "{%0,%1}, {%2,%3,%4,%5}, {%6,%7}, {%0,%1};"
                 : "+r"(d[0]), "+r"(d[1])
                 : "r"(a[0]), "r"(a[1]), "r"(a[2]), "r"(a[3]), "r"(b0), "r"(b1));
}
__device__ __forceinline__ unsigned short tanh_h2_e4m3(uint32_t h) {
    asm("tanh.approx.f16x2 %0, %0;" : "+r"(h));
    unsigned short e;
    asm("cvt.rn.satfinite.e4m3x2.f16x2 %0, %1;" : "=h"(e) : "r"(h));
    return e;
}
__device__ __forceinline__ uint32_t packh2(float lo, float hi) {
    uint32_t h;
    asm("cvt.rn.f16x2.f32 %0, %1, %2;" : "=r"(h) : "f"(hi), "f"(lo));
    return h;
}
__device__ __forceinline__ uint32_t pack4_e4m3(float v0, float v1, float v2, float v3) {
    unsigned short lo, hi;
    asm("cvt.rn.satfinite.e4m3x2.f32 %0, %1, %2;" : "=h"(lo) : "f"(v1), "f"(v0));
    asm("cvt.rn.satfinite.e4m3x2.f32 %0, %1, %2;" : "=h"(hi) : "f"(v3), "f"(v2));
    uint32_t r;
    asm("mov.b32 %0, {%1,%2};" : "=r"(r) : "h"(lo), "h"(hi));
    return r;
}

// ---------------- K0 merged: blocks<256 row stats (1024 thr); blocks>=256 weight packing ----------------
__global__ void k_pre(const float* __restrict__ prim,
                      const float* __restrict__ W2, const float* __restrict__ W3) {
    int tid = threadIdx.x;
    int nthr = blockDim.x;
    if (blockIdx.x < 256) {
        int row = blockIdx.x;
        const float4* p4 = reinterpret_cast<const float4*>(prim + (size_t)row * LROW);
        float mn = 3.4e38f, mx = -3.4e38f;
        for (int i = tid; i < LROW / 4; i += nthr) {
            float4 v = p4[i];
            mn = fminf(mn, fminf(fminf(v.x, v.y), fminf(v.z, v.w)));
            mx = fmaxf(mx, fmaxf(fmaxf(v.x, v.y), fmaxf(v.z, v.w)));
        }
        for (int o = 16; o; o >>= 1) {
            mn = fminf(mn, __shfl_xor_sync(0xffffffffu, mn, o));
            mx = fmaxf(mx, __shfl_xor_sync(0xffffffffu, mx, o));
        }
        __shared__ float smn[32], smx[32];
        if ((tid & 31) == 0) { smn[tid >> 5] = mn; smx[tid >> 5] = mx; }
        __syncthreads();
        if (tid == 0) {
            int nw = nthr >> 5;
            for (int w = 1; w < nw; w++) { mn = fminf(mn, smn[w]); mx = fmaxf(mx, smx[w]); }
            g_stat[2 * row]     = mn;
            g_stat[2 * row + 1] = 1.0f / fmaxf((mx - mn) * 0.5f, 1e-4f);
        }
    } else {
        int base = (blockIdx.x - 256) * nthr + tid;
        int nth = 24 * nthr;
        // layout: i = ((kb*8+nb)*32+lane)*2 + r  (R9 layout)
        for (int i = base; i < 10 * 8 * 32 * 2; i += nth) {
            int r = i & 1, lane = (i >> 1) & 31, nb = (i >> 6) & 7, kb = i >> 9;
            int tg = lane & 3, gg = lane >> 2;
            int kshift = kb >> 1;
            int ci = (kb & 1) * 32 + r * 16 + tg * 4;
            int co = nb * 8 + gg;
            const float* wb = W2 + kshift * 4096 + ci * 64 + co;
            g_w2f[i] = pack4_e4m3(wb[0], wb[64], wb[128], wb[192]);
        }
        for (int i = base; i < 10 * 32 * 2; i += nth) {
            int r = i & 1, lane = (i >> 1) & 31, kb = i >> 6;
            int tg = lane & 3, gg = lane >> 2;
            int kshift = kb >> 1;
            int ci = (kb & 1) * 32 + r * 16 + tg * 4;
            float v0 = 0, v1 = 0, v2 = 0, v3 = 0;
            if (gg < 4) {
                const float* wb = W3 + kshift * 256 + ci * 4 + gg;
                v0 = wb[0]; v1 = wb[4]; v2 = wb[8]; v3 = wb[12];
            }
            g_w3f[i] = pack4_e4m3(v0, v1, v2, v3);
        }
    }
}

// ---------------- mega kernel ----------------
__global__ void __launch_bounds__(256, 4)
k_mega(const float* __restrict__ prim,
       const float* __restrict__ W1g, const float* __restrict__ b1g,
       const float* __restrict__ b2g, const float* __restrict__ b3g,
       float* __restrict__ out) {
    extern __shared__ __align__(16) char smem[];
    int tid = threadIdx.x;
    int w = tid >> 5, lane = tid & 31;
    int tg = lane & 3, gg = lane >> 2;
    int row = blockIdx.y;
    int t0 = blockIdx.x * OUT_TILE;
    size_t rb = (size_t)row * LROW;

    uint32_t sh_base = smem_u32(smem) + OFF_H;
    float* sPrim = reinterpret_cast<float*>(smem + OFF_PRIM);
    float* sy    = reinterpret_cast<float*>(smem + OFF_Y);
    float* sb2   = reinterpret_cast<float*>(smem + OFF_B2);
    float* sb3   = reinterpret_cast<float*>(smem + OFF_B3);
    float* scoef = reinterpret_cast<float*>(smem + OFF_COEF);
    float* sg    = reinterpret_cast<float*>(smem + OFF_G);
    float* sf    = reinterpret_cast<float*>(smem + OFF_F);

    // ---- phase 0: async weight staging + prim + rescale ----
    {
        uint32_t w2s = smem_u32(smem) + OFF_W2F;
        const char* w2g = reinterpret_cast<const char*>(g_w2f);
        for (int i = tid; i < 1280; i += 256)
            cp_async16(w2s + i * 16, w2g + (size_t)i * 16);
        uint32_t w3s = smem_u32(smem) + OFF_W3F;
        const char* w3g = reinterpret_cast<const char*>(g_w3f);
        if (tid < 160)
            cp_async16(w3s + tid * 16, w3g + (size_t)tid * 16);
        asm volatile("cp.async.commit_group;" ::: "memory");

        float mn = g_stat[2 * row], inv = g_stat[2 * row + 1];
        for (int j = tid; j < 264; j += 256) {
            float p = prim[rb + ((t0 - 8 + j) & (LROW - 1))];
            sPrim[j] = p;
            sy[j] = (p - mn) * inv - 1.0f;
        }
        if (tid < 64) sb2[tid] = b2g[tid];
        if (tid < 4)  sb3[tid] = b3g[tid];
    }
    // conv1 weights into registers (global loads; lane = channel pair)
    __half2 hw[5], hbr;
    {
        float2 bv = *reinterpret_cast<const float2*>(b1g + 2 * lane);
        uint32_t u = packh2(bv.x, bv.y);
        hbr = *reinterpret_cast<__half2*>(&u);
#pragma unroll
        for (int k = 0; k < 5; k++) {
            float2 wv = *reinterpret_cast<const float2*>(W1g + k * 64 + 2 * lane);
            uint32_t uu = packh2(wv.x, wv.y);
            hw[k] = *reinterpret_cast<__half2*>(&uu);
        }
    }
    __syncthreads();

    // ---- phase 1: conv1 (half2, weights in regs, sliding window) -> sH1 ----
    {
        int j0 = w * 33;
        int jend = j0 + 33 < HROWS ? j0 + 33 : HROWS;
        __half2 hy[5];
#pragma unroll
        for (int i = 0; i < 5; i++) hy[i] = __float2half2_rn(sy[j0 + i]);
        for (int j = j0; j < jend; j++) {
            __half2 a = hbr;
            a = __hfma2(hy[0], hw[0], a);
            a = __hfma2(hy[1], hw[1], a);
            a = __hfma2(hy[2], hw[2], a);
            a = __hfma2(hy[3], hw[3], a);
            a = __hfma2(hy[4], hw[4], a);
            sts16(sh_base + j * 80 + lane * 2,
                  tanh_h2_e4m3(*reinterpret_cast<uint32_t*>(&a)));
            hy[0] = hy[1]; hy[1] = hy[2]; hy[2] = hy[3]; hy[3] = hy[4];
            hy[4] = __float2half2_rn(sy[j + 5]);
        }
    }
    asm volatile("cp.async.wait_group 0;" ::: "memory");
    __syncthreads();

    // ---- phase 2: conv2 fp8 MMA, f16 accum (M=256, N=64, K=320) ----
    int m0 = w * 32;
    uint32_t acc[2][8][2];
#pragma unroll
    for (int nb = 0; nb < 8; nb++) {
        uint32_t binit = packh2(sb2[nb * 8 + tg * 2], sb2[nb * 8 + tg * 2 + 1]);
#pragma unroll
        for (int mt = 0; mt < 2; mt++) { acc[mt][nb][0] = binit; acc[mt][nb][1] = binit; }
    }
#pragma unroll 5
    for (int kb = 0; kb < 10; kb++) {
        int kshift = kb >> 1;
        uint32_t off = (uint32_t)((kb & 1) * 32 + ((lane >> 4) << 4));
        uint32_t a[2][4];
#pragma unroll
        for (int mt = 0; mt < 2; mt++) {
            uint32_t r = (uint32_t)(m0 + mt * 16 + (lane & 15) + kshift);
            ldmatrix_x4(a[mt], sh_base + r * 80 + off);
        }
#pragma unroll
        for (int nb = 0; nb < 8; nb++) {
            uint2 b = *reinterpret_cast<const uint2*>(
                smem + OFF_W2F + (size_t)(((kb << 3) + nb) * 32 + lane) * 8);
            mma_fp8_h(acc[0][nb], a[0], b.x, b.y);
            mma_fp8_h(acc[1][nb], a[1], b.x, b.y);
        }
    }

    // ---- phase 3: tanh epilogue directly on f16x2 accums -> sH2 (overlay) ----
    unsigned short h2e[2][8][2];
#pragma unroll
    for (int mt = 0; mt < 2; mt++)
#pragma unroll
        for (int nb = 0; nb < 8; nb++) {
            h2e[mt][nb][0] = tanh_h2_e4m3(acc[mt][nb][0]);
            h2e[mt][nb][1] = tanh_h2_e4m3(acc[mt][nb][1]);
        }
    __syncthreads();   // all warps done reading sH1
#pragma unroll
    for (int mt = 0; mt < 2; mt++) {
        uint32_t r0 = (uint32_t)(m0 + mt * 16 + gg);
#pragma unroll
        for (int nb = 0; nb < 8; nb++) {
            uint32_t cb = (uint32_t)(nb * 8 + tg * 2);
            sts16(sh_base + r0 * 80 + cb, h2e[mt][nb][0]);
            sts16(sh_base + (r0 + 8) * 80 + cb, h2e[mt][nb][1]);
        }
    }
    __syncthreads();

    // ---- phase 4: conv3 fp8 MMA, f16 accum (M=256, N=8pad, K=320) -> coeffs ----
    uint32_t acc3[2][2];
    {
        uint32_t bz = (tg < 2) ? packh2(sb3[tg * 2], sb3[tg * 2 + 1]) : 0u;
#pragma unroll
        for (int mt = 0; mt < 2; mt++) { acc3[mt][0] = bz; acc3[mt][1] = bz; }
    }
#pragma unroll 5
    for (int kb = 0; kb < 10; kb++) {
        int kshift = kb >> 1;
        uint32_t off = (uint32_t)((kb & 1) * 32 + ((lane >> 4) << 4));
        uint32_t a[2][4];
#pragma unroll
        for (int mt = 0; mt < 2; mt++) {
            uint32_t r = (uint32_t)(m0 + mt * 16 + (lane & 15) + kshift);
            ldmatrix_x4(a[mt], sh_base + r * 80 + off);
        }
        uint2 b = *reinterpret_cast<const uint2*>(
            smem + OFF_W3F + (size_t)((kb << 5) + lane) * 8);
        mma_fp8_h(acc3[0], a[0], b.x, b.y);
        mma_fp8_h(acc3[1], a[1], b.x, b.y);
    }
    if (tg < 2) {
#pragma unroll
        for (int mt = 0; mt < 2; mt++) {
            int p = m0 + mt * 16 + gg;
            int c0 = tg * 2;
            float2 v01 = __half22float2(*reinterpret_cast<__half2*>(&acc3[mt][0]));
            float2 v23 = __half22float2(*reinterpret_cast<__half2*>(&acc3[mt][1]));
            scoef[p * 4 + c0]           = v01.x;
            scoef[p * 4 + c0 + 1]       = v01.y;
            scoef[(p + 8) * 4 + c0]     = v23.x;
            scoef[(p + 8) * 4 + c0 + 1] = v23.y;
        }
    }
    __syncthreads();

    // ---- phase 5: alpha -> grad -> TVD flux -> update ----
    if (tid < 252) {   // grad at position t0-2+tid
        float4 c = *reinterpret_cast<const float4*>(scoef + tid * 4);
        float S = c.x + c.y + c.z + c.w;
        const float NB0 = -0.44721359549995793f;
        const float NBD = -0.13819660112501052f;
        float a0 = (float)( 1.0 / 12.0) + NB0 * S;
        float a1 = (float)(-2.0 / 3.0)  + c.x + NBD * S;
        float a2 =                        c.y + NBD * S;
        float a3 = (float)( 2.0 / 3.0)  + c.z + NBD * S;
        float a4 = (float)(-1.0 / 12.0) + c.w + NBD * S;
        float g = sPrim[tid + 4] * a0 + sPrim[tid + 5] * a1 + sPrim[tid + 6] * a2
                + sPrim[tid + 7] * a3 + sPrim[tid + 8] * a4;
        sg[tid] = g * 64.0f;
    }
    __syncthreads();
    if (tid < 250) {   // flux at position t0-1+tid
        float gm1 = sg[tid], g0 = sg[tid + 1], g1 = sg[tid + 2];
        float aa0 = (g0 < 0.0f) ? -1.0f : 1.0f;
        float ri0 = gm1 / (fmaxf(fabsf(g0), 1e-15f) * aa0);
        float phi0 = (ri0 * ri0 + ri0) / (ri0 * ri0 + 1.0f);
        float aa1 = (g1 < 0.0f) ? -1.0f : 1.0f;
        float ri1 = g0 / (fmaxf(fabsf(g1), 1e-15f) * aa1);
        float phi1 = (ri1 * ri1 + ri1) / (ri1 * ri1 + 1.0f);
        float uL = sPrim[tid + 7] + 0.0078125f * phi0 * g0;
        float uR = sPrim[tid + 8] - 0.0078125f * phi1 * g1;
        sf[tid] = 0.25f * (uL * uL + uR * uR) - 0.25f * fabsf(uL + uR) * (uR - uL);
    }
    __syncthreads();
    if (tid < OUT_TILE) {
        int o = t0 + tid;
        if (o < LROW)
            out[rb + o] = sPrim[tid + 8] - 0.01f * (sf[tid + 1] - sf[tid]);
    }
}

// ---------------- launch ----------------
extern "C" void kernel_launch(void* const* d_in, const int* in_sizes, int n_in,
                              void* d_out, int out_size) {
    const float* Prim = (const float*)d_in[0];
    const float* W1   = (const float*)d_in[1];
    const float* b1   = (const float*)d_in[2];
    const float* W2   = (const float*)d_in[3];
    const float* b2   = (const float*)d_in[4];
    const float* W3   = (const float*)d_in[5];
    const float* b3   = (const float*)d_in[6];
    float* out = (float*)d_out;

    cudaFuncSetAttribute(k_mega, cudaFuncAttributeMaxDynamicSharedMemorySize, SMEM_TOTAL);

    k_pre<<<280, 1024>>>(Prim, W2, W3);
    k_mega<<<dim3(NTILES, NROWS), 256, SMEM_TOTAL>>>(Prim, W1, b1, b2, b3, out);
}

// round 14
// speedup vs baseline: 3.9690x; 1.0888x over previous
#include <cuda_runtime.h>
#include <cuda_bf16.h>
#include <cuda_fp16.h>
#include <cstdint>

#define LROW 8192
#define NROWS 256
#define OUT_TILE 249
#define NTILES 33   // 33*249 = 8217 >= 8192
#define HROWS 260

// ---------------- device globals ----------------
static __device__ __align__(16) uint32_t g_w2f[10 * 8 * 32 * 2];  // conv2 e4m3 B-frags [kb][nb][lane][2]
static __device__ __align__(16) uint32_t g_w3f[10 * 32 * 2];      // conv3 e4m3 B-frags [kb][lane][2]
static __device__ float    g_stat[NROWS * 2];

// ---------------- smem layout (bytes) ----------------
// H rows: 260 x 80B (64 e4m3 + 16B pad; stride 80 => conflict-free ldmatrix)
#define OFF_H    0                    // 20800
#define OFF_W2F  20800                // 20480
#define OFF_W3F  (OFF_W2F + 20480)   // 41280: 2560
#define OFF_PRIM (OFF_W3F + 2560)    // 43840: 264 f32 -> 1056
#define OFF_Y    (OFF_PRIM + 1056)   // 44896: 264 f32 -> 1056
#define OFF_B2   (OFF_Y + 1056)      // 45952: 256
#define OFF_B3   (OFF_B2 + 256)      // 46208: 32
#define OFF_COEF (OFF_B3 + 32)       // 46240: 256 x float4 -> 4096
#define OFF_G    (OFF_COEF + 4096)   // 50336: 1024
#define OFF_F    (OFF_G + 1024)      // 51360: 1024
#define SMEM_TOTAL (OFF_F + 1024)    // 52384 (x4 = 209.5 KB/SM)

// ---------------- helpers ----------------
__device__ __forceinline__ uint32_t smem_u32(const void* p) {
    uint32_t a;
    asm("{ .reg .u64 t; cvta.to.shared.u64 t, %1; cvt.u32.u64 %0, t; }" : "=r"(a) : "l"(p));
    return a;
}
__device__ __forceinline__ void sts16(uint32_t a, unsigned short v) {
    asm volatile("st.shared.b16 [%0], %1;" :: "r"(a), "h"(v) : "memory");
}
__device__ __forceinline__ void cp_async16(uint32_t dst, const void* src) {
    asm volatile("cp.async.cg.shared.global [%0], [%1], 16;" :: "r"(dst), "l"(src) : "memory");
}
__device__ __forceinline__ void ldmatrix_x4(uint32_t* r, uint32_t a) {
    asm volatile("ldmatrix.sync.aligned.m8n8.x4.shared.b16 {%0,%1,%2,%3}, [%4];"
                 : "=r"(r[0]), "=r"(r[1]), "=r"(r[2]), "=r"(r[3]) : "r"(a));
}
__device__ __forceinline__ void mma_fp8_h(uint32_t* d, const uint32_t* a, uint32_t b0, uint32_t b1) {
    asm volatile("mma.sync.aligned.m16n8k32.row.col.f16.e4m3.e4m3.f16 "
                 "{%0,%1}, {%2,%3,%4,%5}, {%6,%7}, {%0,%1};"
                 : "+r"(d[0]), "+r"(d[1])
                 : "r"(a[0]), "r"(a[1]), "r"(a[2]), "r"(a[3]), "r"(b0), "r"(b1));
}
__device__ __forceinline__ unsigned short tanh_h2_e4m3(uint32_t h) {
    asm("tanh.approx.f16x2 %0, %0;" : "+r"(h));
    unsigned short e;
    asm("cvt.rn.satfinite.e4m3x2.f16x2 %0, %1;" : "=h"(e) : "r"(h));
    return e;
}
__device__ __forceinline__ uint32_t packh2(float lo, float hi) {
    uint32_t h;
    asm("cvt.rn.f16x2.f32 %0, %1, %2;" : "=r"(h) : "f"(hi), "f"(lo));
    return h;
}
__device__ __forceinline__ uint32_t pack4_e4m3(float v0, float v1, float v2, float v3) {
    unsigned short lo, hi;
    asm("cvt.rn.satfinite.e4m3x2.f32 %0, %1, %2;" : "=h"(lo) : "f"(v1), "f"(v0));
    asm("cvt.rn.satfinite.e4m3x2.f32 %0, %1, %2;" : "=h"(hi) : "f"(v3), "f"(v2));
    uint32_t r;
    asm("mov.b32 %0, {%1,%2};" : "=r"(r) : "h"(lo), "h"(hi));
    return r;
}
__device__ __forceinline__ uint2 lds64(const void* p) {
    uint2 v;
    asm volatile("ld.shared.v2.u32 {%0,%1}, [%2];" : "=r"(v.x), "=r"(v.y) : "l"(p));
    return v;
}

// ---------------- K0 merged: blocks<256 row stats (1024 thr); blocks>=256 weight packing ----------------
__global__ void k_pre(const float* __restrict__ prim,
                      const float* __restrict__ W2, const float* __restrict__ W3) {
    int tid = threadIdx.x;
    int nthr = blockDim.x;
    if (blockIdx.x < 256) {
        int row = blockIdx.x;
        const float4* p4 = reinterpret_cast<const float4*>(prim + (size_t)row * LROW);
        float mn = 3.4e38f, mx = -3.4e38f;
        for (int i = tid; i < LROW / 4; i += nthr) {
            float4 v = p4[i];
            mn = fminf(mn, fminf(fminf(v.x, v.y), fminf(v.z, v.w)));
            mx = fmaxf(mx, fmaxf(fmaxf(v.x, v.y), fmaxf(v.z, v.w)));
        }
        for (int o = 16; o; o >>= 1) {
            mn = fminf(mn, __shfl_xor_sync(0xffffffffu, mn, o));
            mx = fmaxf(mx, __shfl_xor_sync(0xffffffffu, mx, o));
        }
        __shared__ float smn[32], smx[32];
        if ((tid & 31) == 0) { smn[tid >> 5] = mn; smx[tid >> 5] = mx; }
        __syncthreads();
        if (tid == 0) {
            int nw = nthr >> 5;
            for (int w = 1; w < nw; w++) { mn = fminf(mn, smn[w]); mx = fmaxf(mx, smx[w]); }
            g_stat[2 * row]     = mn;
            g_stat[2 * row + 1] = 1.0f / fmaxf((mx - mn) * 0.5f, 1e-4f);
        }
    } else {
        int base = (blockIdx.x - 256) * nthr + tid;
        int nth = 24 * nthr;
        for (int i = base; i < 10 * 8 * 32 * 2; i += nth) {
            int r = i & 1, lane = (i >> 1) & 31, nb = (i >> 6) & 7, kb = i >> 9;
            int tg = lane & 3, gg = lane >> 2;
            int kshift = kb >> 1;
            int ci = (kb & 1) * 32 + r * 16 + tg * 4;
            int co = nb * 8 + gg;
            const float* wb = W2 + kshift * 4096 + ci * 64 + co;
            g_w2f[i] = pack4_e4m3(wb[0], wb[64], wb[128], wb[192]);
        }
        for (int i = base; i < 10 * 32 * 2; i += nth) {
            int r = i & 1, lane = (i >> 1) & 31, kb = i >> 6;
            int tg = lane & 3, gg = lane >> 2;
            int kshift = kb >> 1;
            int ci = (kb & 1) * 32 + r * 16 + tg * 4;
            float v0 = 0, v1 = 0, v2 = 0, v3 = 0;
            if (gg < 4) {
                const float* wb = W3 + kshift * 256 + ci * 4 + gg;
                v0 = wb[0]; v1 = wb[4]; v2 = wb[8]; v3 = wb[12];
            }
            g_w3f[i] = pack4_e4m3(v0, v1, v2, v3);
        }
    }
}

// ---------------- mega kernel ----------------
__global__ void __launch_bounds__(256, 4)
k_mega(const float* __restrict__ prim,
       const float* __restrict__ W1g, const float* __restrict__ b1g,
       const float* __restrict__ b2g, const float* __restrict__ b3g,
       float* __restrict__ out) {
    extern __shared__ __align__(16) char smem[];
    int tid = threadIdx.x;
    int w = tid >> 5, lane = tid & 31;
    int tg = lane & 3, gg = lane >> 2;
    int row = blockIdx.y;
    int t0 = blockIdx.x * OUT_TILE;
    size_t rb = (size_t)row * LROW;

    uint32_t sh_base = smem_u32(smem) + OFF_H;
    float* sPrim = reinterpret_cast<float*>(smem + OFF_PRIM);
    float* sy    = reinterpret_cast<float*>(smem + OFF_Y);
    float* sb2   = reinterpret_cast<float*>(smem + OFF_B2);
    float* sb3   = reinterpret_cast<float*>(smem + OFF_B3);
    float* scoef = reinterpret_cast<float*>(smem + OFF_COEF);
    float* sg    = reinterpret_cast<float*>(smem + OFF_G);
    float* sf    = reinterpret_cast<float*>(smem + OFF_F);

    // ---- phase 0: async weight staging + prim + rescale ----
    {
        uint32_t w2s = smem_u32(smem) + OFF_W2F;
        const char* w2g = reinterpret_cast<const char*>(g_w2f);
        for (int i = tid; i < 1280; i += 256)
            cp_async16(w2s + i * 16, w2g + (size_t)i * 16);
        uint32_t w3s = smem_u32(smem) + OFF_W3F;
        const char* w3g = reinterpret_cast<const char*>(g_w3f);
        if (tid < 160)
            cp_async16(w3s + tid * 16, w3g + (size_t)tid * 16);
        asm volatile("cp.async.commit_group;" ::: "memory");

        float mn = g_stat[2 * row], inv = g_stat[2 * row + 1];
        for (int j = tid; j < 264; j += 256) {
            float p = prim[rb + ((t0 - 8 + j) & (LROW - 1))];
            sPrim[j] = p;
            sy[j] = (p - mn) * inv - 1.0f;
        }
        if (tid < 64) sb2[tid] = b2g[tid];
        if (tid < 4)  sb3[tid] = b3g[tid];
    }
    // conv1 weights into registers (global loads; lane = channel pair)
    __half2 hw[5], hbr;
    {
        float2 bv = *reinterpret_cast<const float2*>(b1g + 2 * lane);
        uint32_t u = packh2(bv.x, bv.y);
        hbr = *reinterpret_cast<__half2*>(&u);
#pragma unroll
        for (int k = 0; k < 5; k++) {
            float2 wv = *reinterpret_cast<const float2*>(W1g + k * 64 + 2 * lane);
            uint32_t uu = packh2(wv.x, wv.y);
            hw[k] = *reinterpret_cast<__half2*>(&uu);
        }
    }
    __syncthreads();

    // ---- phase 1: conv1 (half2, weights in regs, sliding window) -> sH1 ----
    {
        int j0 = w * 33;
        int jend = j0 + 33 < HROWS ? j0 + 33 : HROWS;
        __half2 hy[5];
#pragma unroll
        for (int i = 0; i < 5; i++) hy[i] = __float2half2_rn(sy[j0 + i]);
        uint32_t adr = sh_base + j0 * 80 + lane * 2;
        for (int j = j0; j < jend; j++) {
            __half2 a = hbr;
            a = __hfma2(hy[0], hw[0], a);
            a = __hfma2(hy[1], hw[1], a);
            a = __hfma2(hy[2], hw[2], a);
            a = __hfma2(hy[3], hw[3], a);
            a = __hfma2(hy[4], hw[4], a);
            sts16(adr, tanh_h2_e4m3(*reinterpret_cast<uint32_t*>(&a)));
            adr += 80;
            hy[0] = hy[1]; hy[1] = hy[2]; hy[2] = hy[3]; hy[3] = hy[4];
            hy[4] = __float2half2_rn(sy[j + 5]);
        }
    }
    asm volatile("cp.async.wait_group 0;" ::: "memory");
    __syncthreads();

    // ---- phase 2: conv2 fp8 MMA, f16 accum (M=256, N=64, K=320) ----
    // All loop addresses are base + compile-time immediates (full unroll).
    int m0 = w * 32;
    uint32_t aAddr = sh_base + (uint32_t)((m0 + (lane & 15)) * 80 + ((lane >> 4) << 4));
    const char* w2p = smem + OFF_W2F + lane * 8;
    const char* w3p = smem + OFF_W3F + lane * 8;

    uint32_t acc[2][8][2];
#pragma unroll
    for (int nb = 0; nb < 8; nb++) {
        uint32_t binit = packh2(sb2[nb * 8 + tg * 2], sb2[nb * 8 + tg * 2 + 1]);
#pragma unroll
        for (int mt = 0; mt < 2; mt++) { acc[mt][nb][0] = binit; acc[mt][nb][1] = binit; }
    }
#pragma unroll
    for (int kb = 0; kb < 10; kb++) {
        uint32_t a[2][4];
        uint32_t ad = aAddr + (uint32_t)((kb >> 1) * 80 + (kb & 1) * 32);
        ldmatrix_x4(a[0], ad);
        ldmatrix_x4(a[1], ad + 1280);
#pragma unroll
        for (int nb = 0; nb < 8; nb++) {
            uint2 b = lds64(w2p + ((kb * 8 + nb) * 32) * 8);
            mma_fp8_h(acc[0][nb], a[0], b.x, b.y);
            mma_fp8_h(acc[1][nb], a[1], b.x, b.y);
        }
    }

    // ---- phase 3: tanh epilogue directly on f16x2 accums -> sH2 (overlay) ----
    unsigned short h2e[2][8][2];
#pragma unroll
    for (int mt = 0; mt < 2; mt++)
#pragma unroll
        for (int nb = 0; nb < 8; nb++) {
            h2e[mt][nb][0] = tanh_h2_e4m3(acc[mt][nb][0]);
            h2e[mt][nb][1] = tanh_h2_e4m3(acc[mt][nb][1]);
        }
    __syncthreads();   // all warps done reading sH1
    {
        uint32_t sAddr = sh_base + (uint32_t)((m0 + gg) * 80 + tg * 2);
#pragma unroll
        for (int mt = 0; mt < 2; mt++)
#pragma unroll
            for (int nb = 0; nb < 8; nb++) {
                sts16(sAddr + (uint32_t)(mt * 1280 + nb * 8), h2e[mt][nb][0]);
                sts16(sAddr + (uint32_t)(mt * 1280 + 640 + nb * 8), h2e[mt][nb][1]);
            }
    }
    __syncthreads();

    // ---- phase 4: conv3 fp8 MMA, f16 accum (M=256, N=8pad, K=320) -> coeffs ----
    uint32_t acc3[2][2];
    {
        uint32_t bz = (tg < 2) ? packh2(sb3[tg * 2], sb3[tg * 2 + 1]) : 0u;
#pragma unroll
        for (int mt = 0; mt < 2; mt++) { acc3[mt][0] = bz; acc3[mt][1] = bz; }
    }
#pragma unroll
    for (int kb = 0; kb < 10; kb++) {
        uint32_t a[2][4];
        uint32_t ad = aAddr + (uint32_t)((kb >> 1) * 80 + (kb & 1) * 32);
        ldmatrix_x4(a[0], ad);
        ldmatrix_x4(a[1], ad + 1280);
        uint2 b = lds64(w3p + (kb * 32) * 8);
        mma_fp8_h(acc3[0], a[0], b.x, b.y);
        mma_fp8_h(acc3[1], a[1], b.x, b.y);
    }
    if (tg < 2) {
#pragma unroll
        for (int mt = 0; mt < 2; mt++) {
            int p = m0 + mt * 16 + gg;
            int c0 = tg * 2;
            float2 v01 = __half22float2(*reinterpret_cast<__half2*>(&acc3[mt][0]));
            float2 v23 = __half22float2(*reinterpret_cast<__half2*>(&acc3[mt][1]));
            scoef[p * 4 + c0]           = v01.x;
            scoef[p * 4 + c0 + 1]       = v01.y;
            scoef[(p + 8) * 4 + c0]     = v23.x;
            scoef[(p + 8) * 4 + c0 + 1] = v23.y;
        }
    }
    __syncthreads();

    // ---- phase 5: alpha -> grad -> TVD flux -> update ----
    if (tid < 252) {   // grad at position t0-2+tid
        float4 c = *reinterpret_cast<const float4*>(scoef + tid * 4);
        float S = c.x + c.y + c.z + c.w;
        const float NB0 = -0.44721359549995793f;
        const float NBD = -0.13819660112501052f;
        float a0 = (float)( 1.0 / 12.0) + NB0 * S;
        float a1 = (float)(-2.0 / 3.0)  + c.x + NBD * S;
        float a2 =                        c.y + NBD * S;
        float a3 = (float)( 2.0 / 3.0)  + c.z + NBD * S;
        float a4 = (float)(-1.0 / 12.0) + c.w + NBD * S;
        float g = sPrim[tid + 4] * a0 + sPrim[tid + 5] * a1 + sPrim[tid + 6] * a2
                + sPrim[tid + 7] * a3 + sPrim[tid + 8] * a4;
        sg[tid] = g * 64.0f;
    }
    __syncthreads();
    if (tid < 250) {   // flux at position t0-1+tid
        float gm1 = sg[tid], g0 = sg[tid + 1], g1 = sg[tid + 2];
        float aa0 = (g0 < 0.0f) ? -1.0f : 1.0f;
        float ri0 = gm1 / (fmaxf(fabsf(g0), 1e-15f) * aa0);
        float phi0 = (ri0 * ri0 + ri0) / (ri0 * ri0 + 1.0f);
        float aa1 = (g1 < 0.0f) ? -1.0f : 1.0f;
        float ri1 = g0 / (fmaxf(fabsf(g1), 1e-15f) * aa1);
        float phi1 = (ri1 * ri1 + ri1) / (ri1 * ri1 + 1.0f);
        float uL = sPrim[tid + 7] + 0.0078125f * phi0 * g0;
        float uR = sPrim[tid + 8] - 0.0078125f * phi1 * g1;
        sf[tid] = 0.25f * (uL * uL + uR * uR) - 0.25f * fabsf(uL + uR) * (uR - uL);
    }
    __syncthreads();
    if (tid < OUT_TILE) {
        int o = t0 + tid;
        if (o < LROW)
            out[rb + o] = sPrim[tid + 8] - 0.01f * (sf[tid + 1] - sf[tid]);
    }
}

// ---------------- launch ----------------
extern "C" void kernel_launch(void* const* d_in, const int* in_sizes, int n_in,
                              void* d_out, int out_size) {
    const float* Prim = (const float*)d_in[0];
    const float* W1   = (const float*)d_in[1];
    const float* b1   = (const float*)d_in[2];
    const float* W2   = (const float*)d_in[3];
    const float* b2   = (const float*)d_in[4];
    const float* W3   = (const float*)d_in[5];
    const float* b3   = (const float*)d_in[6];
    float* out = (float*)d_out;

    cudaFuncSetAttribute(k_mega, cudaFuncAttributeMaxDynamicSharedMemorySize, SMEM_TOTAL);

    k_pre<<<280, 1024>>>(Prim, W2, W3);
    k_mega<<<dim3(NTILES, NROWS), 256, SMEM_TOTAL>>>(Prim, W1, b1, b2, b3, out);
}

// round 15
// speedup vs baseline: 4.0305x; 1.0155x over previous
#include <cuda_runtime.h>
#include <cuda_bf16.h>
#include <cuda_fp16.h>
#include <cstdint>

#define LROW 8192
#define NROWS 256
#define OUT_TILE 249
#define NTILES 33   // 33*249 = 8217 >= 8192
#define HROWS 260

// ---------------- device globals ----------------
static __device__ __align__(16) uint32_t g_w2f[10 * 8 * 32 * 2];  // conv2 e4m3 B-frags [kb][nb][lane][2]
static __device__ __align__(16) uint32_t g_w3f[10 * 32 * 2];      // conv3 e4m3 B-frags [kb][lane][2]
static __device__ float    g_stat[NROWS * 2];

// ---------------- smem layout (bytes) ----------------
// H rows: 264 x 80B (64 e4m3 + 16B pad; stride 80 => conflict-free ldmatrix)
// rows 260..263 are scratch (written by fixed-trip conv1, never read).
#define OFF_H    0                    // 21120
#define OFF_W2F  21120                // 20480
#define OFF_W3F  (OFF_W2F + 20480)   // 41600: 2560
#define OFF_PRIM (OFF_W3F + 2560)    // 44160: 264 f32 -> 1056
#define OFF_Y    (OFF_PRIM + 1056)   // 45216: 272 u32 (f16x2 dup; 264 valid + pad) -> 1088
#define OFF_B2   (OFF_Y + 1088)      // 46304: 256
#define OFF_B3   (OFF_B2 + 256)      // 46560: 32
#define OFF_COEF (OFF_B3 + 32)       // 46592: 256 x float4 -> 4096
#define OFF_G    (OFF_COEF + 4096)   // 50688: 1024
#define OFF_F    (OFF_G + 1024)      // 51712: 1024
#define SMEM_TOTAL (OFF_F + 1024)    // 52736 (x4 = 210.9 KB/SM)

// ---------------- helpers ----------------
__device__ __forceinline__ uint32_t smem_u32(const void* p) {
    uint32_t a;
    asm("{ .reg .u64 t; cvta.to.shared.u64 t, %1; cvt.u32.u64 %0, t; }" : "=r"(a) : "l"(p));
    return a;
}
__device__ __forceinline__ void sts16(uint32_t a, unsigned short v) {
    asm volatile("st.shared.b16 [%0], %1;" :: "r"(a), "h"(v) : "memory");
}
__device__ __forceinline__ void cp_async16(uint32_t dst, const void* src) {
    asm volatile("cp.async.cg.shared.global [%0], [%1], 16;" :: "r"(dst), "l"(src) : "memory");
}
__device__ __forceinline__ void ldmatrix_x4(uint32_t* r, uint32_t a) {
    asm volatile("ldmatrix.sync.aligned.m8n8.x4.shared.b16 {%0,%1,%2,%3}, [%4];"
                 : "=r"(r[0]), "=r"(r[1]), "=r"(r[2]), "=r"(r[3]) : "r"(a));
}
__device__ __forceinline__ void mma_fp8_h(uint32_t* d, const uint32_t* a, uint32_t b0, uint32_t b1) {
    asm volatile("mma.sync.aligned.m16n8k32.row.col.f16.e4m3.e4m3.f16 "
                 "{%0,%1}, {%2,%3,%4,%5}, {%6,%7}, {%0,%1};"
                 : "+r"(d[0]), "+r"(d[1])
                 : "r"(a[0]), "r"(a[1]), "r"(a[2]), "r"(a[3]), "r"(b0), "r"(b1));
}
__device__ __forceinline__ unsigned short tanh_h2_e4m3(uint32_t h) {
    asm("tanh.approx.f16x2 %0, %0;" : "+r"(h));
    unsigned short e;
    asm("cvt.rn.satfinite.e4m3x2.f16x2 %0, %1;" : "=h"(e) : "r"(h));
    return e;
}
__device__ __forceinline__ uint32_t packh2(float lo, float hi) {
    uint32_t h;
    asm("cvt.rn.f16x2.f32 %0, %1, %2;" : "=r"(h) : "f"(hi), "f"(lo));
    return h;
}
__device__ __forceinline__ uint32_t pack4_e4m3(float v0, float v1, float v2, float v3) {
    unsigned short lo, hi;
    asm("cvt.rn.satfinite.e4m3x2.f32 %0, %1, %2;" : "=h"(lo) : "f"(v1), "f"(v0));
    asm("cvt.rn.satfinite.e4m3x2.f32 %0, %1, %2;" : "=h"(hi) : "f"(v3), "f"(v2));
    uint32_t r;
    asm("mov.b32 %0, {%1,%2};" : "=r"(r) : "h"(lo), "h"(hi));
    return r;
}
__device__ __forceinline__ uint2 lds64(uint32_t a) {
    uint2 v;
    asm volatile("ld.shared.v2.u32 {%0,%1}, [%2];" : "=r"(v.x), "=r"(v.y) : "r"(a));
    return v;
}
__device__ __forceinline__ uint32_t lds32(uint32_t a) {
    uint32_t v;
    asm volatile("ld.shared.u32 %0, [%1];" : "=r"(v) : "r"(a));
    return v;
}

// ---------------- K0 merged: blocks<256 row stats (1024 thr); blocks>=256 weight packing ----------------
__global__ void k_pre(const float* __restrict__ prim,
                      const float* __restrict__ W2, const float* __restrict__ W3) {
    int tid = threadIdx.x;
    int nthr = blockDim.x;
    if (blockIdx.x < 256) {
        int row = blockIdx.x;
        const float4* p4 = reinterpret_cast<const float4*>(prim + (size_t)row * LROW);
        float mn = 3.4e38f, mx = -3.4e38f;
        for (int i = tid; i < LROW / 4; i += nthr) {
            float4 v = p4[i];
            mn = fminf(mn, fminf(fminf(v.x, v.y), fminf(v.z, v.w)));
            mx = fmaxf(mx, fmaxf(fmaxf(v.x, v.y), fmaxf(v.z, v.w)));
        }
        for (int o = 16; o; o >>= 1) {
            mn = fminf(mn, __shfl_xor_sync(0xffffffffu, mn, o));
            mx = fmaxf(mx, __shfl_xor_sync(0xffffffffu, mx, o));
        }
        __shared__ float smn[32], smx[32];
        if ((tid & 31) == 0) { smn[tid >> 5] = mn; smx[tid >> 5] = mx; }
        __syncthreads();
        if (tid == 0) {
            int nw = nthr >> 5;
            for (int w = 1; w < nw; w++) { mn = fminf(mn, smn[w]); mx = fmaxf(mx, smx[w]); }
            g_stat[2 * row]     = mn;
            g_stat[2 * row + 1] = 1.0f / fmaxf((mx - mn) * 0.5f, 1e-4f);
        }
    } else {
        int base = (blockIdx.x - 256) * nthr + tid;
        int nth = 24 * nthr;
        for (int i = base; i < 10 * 8 * 32 * 2; i += nth) {
            int r = i & 1, lane = (i >> 1) & 31, nb = (i >> 6) & 7, kb = i >> 9;
            int tg = lane & 3, gg = lane >> 2;
            int kshift = kb >> 1;
            int ci = (kb & 1) * 32 + r * 16 + tg * 4;
            int co = nb * 8 + gg;
            const float* wb = W2 + kshift * 4096 + ci * 64 + co;
            g_w2f[i] = pack4_e4m3(wb[0], wb[64], wb[128], wb[192]);
        }
        for (int i = base; i < 10 * 32 * 2; i += nth) {
            int r = i & 1, lane = (i >> 1) & 31, kb = i >> 6;
            int tg = lane & 3, gg = lane >> 2;
            int kshift = kb >> 1;
            int ci = (kb & 1) * 32 + r * 16 + tg * 4;
            float v0 = 0, v1 = 0, v2 = 0, v3 = 0;
            if (gg < 4) {
                const float* wb = W3 + kshift * 256 + ci * 4 + gg;
                v0 = wb[0]; v1 = wb[4]; v2 = wb[8]; v3 = wb[12];
            }
            g_w3f[i] = pack4_e4m3(v0, v1, v2, v3);
        }
    }
}

// ---------------- mega kernel ----------------
__global__ void __launch_bounds__(256, 4)
k_mega(const float* __restrict__ prim,
       const float* __restrict__ W1g, const float* __restrict__ b1g,
       const float* __restrict__ b2g, const float* __restrict__ b3g,
       float* __restrict__ out) {
    extern __shared__ __align__(16) char smem[];
    int tid = threadIdx.x;
    int w = tid >> 5, lane = tid & 31;
    int tg = lane & 3, gg = lane >> 2;
    int row = blockIdx.y;
    int t0 = blockIdx.x * OUT_TILE;
    size_t rb = (size_t)row * LROW;

    uint32_t sb32 = smem_u32(smem);
    uint32_t sh_base = sb32 + OFF_H;
    float* sPrim = reinterpret_cast<float*>(smem + OFF_PRIM);
    uint32_t* sy2 = reinterpret_cast<uint32_t*>(smem + OFF_Y);
    float* sb2   = reinterpret_cast<float*>(smem + OFF_B2);
    float* sb3   = reinterpret_cast<float*>(smem + OFF_B3);
    float* scoef = reinterpret_cast<float*>(smem + OFF_COEF);
    float* sg    = reinterpret_cast<float*>(smem + OFF_G);
    float* sf    = reinterpret_cast<float*>(smem + OFF_F);

    // ---- phase 0: async weight staging + prim + rescale (y pre-packed f16x2) ----
    {
        uint32_t w2s = sb32 + OFF_W2F;
        const char* w2g = reinterpret_cast<const char*>(g_w2f);
        for (int i = tid; i < 1280; i += 256)
            cp_async16(w2s + i * 16, w2g + (size_t)i * 16);
        uint32_t w3s = sb32 + OFF_W3F;
        const char* w3g = reinterpret_cast<const char*>(g_w3f);
        if (tid < 160)
            cp_async16(w3s + tid * 16, w3g + (size_t)tid * 16);
        asm volatile("cp.async.commit_group;" ::: "memory");

        float mn = g_stat[2 * row], inv = g_stat[2 * row + 1];
        for (int j = tid; j < 264; j += 256) {
            float p = prim[rb + ((t0 - 8 + j) & (LROW - 1))];
            sPrim[j] = p;
            float y = (p - mn) * inv - 1.0f;
            sy2[j] = packh2(y, y);
        }
        if (tid < 64) sb2[tid] = b2g[tid];
        if (tid < 4)  sb3[tid] = b3g[tid];
    }
    // conv1 weights into registers (global loads; lane = channel pair)
    __half2 hw[5], hbr;
    {
        float2 bv = *reinterpret_cast<const float2*>(b1g + 2 * lane);
        uint32_t u = packh2(bv.x, bv.y);
        hbr = *reinterpret_cast<__half2*>(&u);
#pragma unroll
        for (int k = 0; k < 5; k++) {
            float2 wv = *reinterpret_cast<const float2*>(W1g + k * 64 + 2 * lane);
            uint32_t uu = packh2(wv.x, wv.y);
            hw[k] = *reinterpret_cast<__half2*>(&uu);
        }
    }
    __syncthreads();

    // ---- phase 1: conv1 (half2, weights in regs, fixed 33-row sliding window) ----
    {
        int j0 = w * 33;   // 8*33 = 264 rows; rows 260..263 are scratch
        uint32_t ybase = sb32 + OFF_Y + j0 * 4;
        __half2 hy[5];
#pragma unroll
        for (int i = 0; i < 5; i++) {
            uint32_t u = lds32(ybase + i * 4);
            hy[i] = *reinterpret_cast<__half2*>(&u);
        }
        uint32_t adr = sh_base + j0 * 80 + lane * 2;
#pragma unroll
        for (int s = 0; s < 33; s++) {
            __half2 a = hbr;
            a = __hfma2(hy[0], hw[0], a);
            a = __hfma2(hy[1], hw[1], a);
            a = __hfma2(hy[2], hw[2], a);
            a = __hfma2(hy[3], hw[3], a);
            a = __hfma2(hy[4], hw[4], a);
            sts16(adr + s * 80, tanh_h2_e4m3(*reinterpret_cast<uint32_t*>(&a)));
            hy[0] = hy[1]; hy[1] = hy[2]; hy[2] = hy[3]; hy[3] = hy[4];
            uint32_t u = lds32(ybase + (s + 5) * 4);
            hy[4] = *reinterpret_cast<__half2*>(&u);
        }
    }
    asm volatile("cp.async.wait_group 0;" ::: "memory");
    __syncthreads();

    // ---- phase 2: conv2 fp8 MMA, f16 accum (M=256, N=64, K=320) ----
    int m0 = w * 32;
    uint32_t aAddr = sh_base + (uint32_t)((m0 + (lane & 15)) * 80 + ((lane >> 4) << 4));
    uint32_t w2p = sb32 + OFF_W2F + lane * 8;
    uint32_t w3p = sb32 + OFF_W3F + lane * 8;

    uint32_t acc[2][8][2];
#pragma unroll
    for (int nb = 0; nb < 8; nb++) {
        uint32_t binit = packh2(sb2[nb * 8 + tg * 2], sb2[nb * 8 + tg * 2 + 1]);
#pragma unroll
        for (int mt = 0; mt < 2; mt++) { acc[mt][nb][0] = binit; acc[mt][nb][1] = binit; }
    }
#pragma unroll
    for (int kb = 0; kb < 10; kb++) {
        uint32_t a[2][4];
        uint32_t ad = aAddr + (uint32_t)((kb >> 1) * 80 + (kb & 1) * 32);
        ldmatrix_x4(a[0], ad);
        ldmatrix_x4(a[1], ad + 1280);
#pragma unroll
        for (int nb = 0; nb < 8; nb++) {
            uint2 b = lds64(w2p + (uint32_t)(((kb * 8 + nb) * 32) * 8));
            mma_fp8_h(acc[0][nb], a[0], b.x, b.y);
            mma_fp8_h(acc[1][nb], a[1], b.x, b.y);
        }
    }

    // ---- phase 3: tanh epilogue directly on f16x2 accums -> sH2 (overlay) ----
    unsigned short h2e[2][8][2];
#pragma unroll
    for (int mt = 0; mt < 2; mt++)
#pragma unroll
        for (int nb = 0; nb < 8; nb++) {
            h2e[mt][nb][0] = tanh_h2_e4m3(acc[mt][nb][0]);
            h2e[mt][nb][1] = tanh_h2_e4m3(acc[mt][nb][1]);
        }
    __syncthreads();   // all warps done reading sH1
    {
        uint32_t sAddr = sh_base + (uint32_t)((m0 + gg) * 80 + tg * 2);
#pragma unroll
        for (int mt = 0; mt < 2; mt++)
#pragma unroll
            for (int nb = 0; nb < 8; nb++) {
                sts16(sAddr + (uint32_t)(mt * 1280 + nb * 8), h2e[mt][nb][0]);
                sts16(sAddr + (uint32_t)(mt * 1280 + 640 + nb * 8), h2e[mt][nb][1]);
            }
    }
    __syncthreads();

    // ---- phase 4: conv3 fp8 MMA, f16 accum (M=256, N=8pad, K=320) -> coeffs ----
    uint32_t acc3[2][2];
    {
        uint32_t bz = (tg < 2) ? packh2(sb3[tg * 2], sb3[tg * 2 + 1]) : 0u;
#pragma unroll
        for (int mt = 0; mt < 2; mt++) { acc3[mt][0] = bz; acc3[mt][1] = bz; }
    }
#pragma unroll
    for (int kb = 0; kb < 10; kb++) {
        uint32_t a[2][4];
        uint32_t ad = aAddr + (uint32_t)((kb >> 1) * 80 + (kb & 1) * 32);
        ldmatrix_x4(a[0], ad);
        ldmatrix_x4(a[1], ad + 1280);
        uint2 b = lds64(w3p + (uint32_t)((kb * 32) * 8));
        mma_fp8_h(acc3[0], a[0], b.x, b.y);
        mma_fp8_h(acc3[1], a[1], b.x, b.y);
    }
    if (tg < 2) {
#pragma unroll
        for (int mt = 0; mt < 2; mt++) {
            int p = m0 + mt * 16 + gg;
            int c0 = tg * 2;
            float2 v01 = __half22float2(*reinterpret_cast<__half2*>(&acc3[mt][0]));
            float2 v23 = __half22float2(*reinterpret_cast<__half2*>(&acc3[mt][1]));
            scoef[p * 4 + c0]           = v01.x;
            scoef[p * 4 + c0 + 1]       = v01.y;
            scoef[(p + 8) * 4 + c0]     = v23.x;
            scoef[(p + 8) * 4 + c0 + 1] = v23.y;
        }
    }
    __syncthreads();

    // ---- phase 5: alpha -> grad -> TVD flux -> update ----
    if (tid < 252) {   // grad at position t0-2+tid
        float4 c = *reinterpret_cast<const float4*>(scoef + tid * 4);
        float S = c.x + c.y + c.z + c.w;
        const float NB0 = -0.44721359549995793f;
        const float NBD = -0.13819660112501052f;
        float a0 = (float)( 1.0 / 12.0) + NB0 * S;
        float a1 = (float)(-2.0 / 3.0)  + c.x + NBD * S;
        float a2 =                        c.y + NBD * S;
        float a3 = (float)( 2.0 / 3.0)  + c.z + NBD * S;
        float a4 = (float)(-1.0 / 12.0) + c.w + NBD * S;
        float g = sPrim[tid + 4] * a0 + sPrim[tid + 5] * a1 + sPrim[tid + 6] * a2
                + sPrim[tid + 7] * a3 + sPrim[tid + 8] * a4;
        sg[tid] = g * 64.0f;
    }
    __syncthreads();
    if (tid < 250) {   // flux at position t0-1+tid
        float gm1 = sg[tid], g0 = sg[tid + 1], g1 = sg[tid + 2];
        float aa0 = (g0 < 0.0f) ? -1.0f : 1.0f;
        float ri0 = gm1 / (fmaxf(fabsf(g0), 1e-15f) * aa0);
        float phi0 = (ri0 * ri0 + ri0) / (ri0 * ri0 + 1.0f);
        float aa1 = (g1 < 0.0f) ? -1.0f : 1.0f;
        float ri1 = g0 / (fmaxf(fabsf(g1), 1e-15f) * aa1);
        float phi1 = (ri1 * ri1 + ri1) / (ri1 * ri1 + 1.0f);
        float uL = sPrim[tid + 7] + 0.0078125f * phi0 * g0;
        float uR = sPrim[tid + 8] - 0.0078125f * phi1 * g1;
        sf[tid] = 0.25f * (uL * uL + uR * uR) - 0.25f * fabsf(uL + uR) * (uR - uL);
    }
    __syncthreads();
    if (tid < OUT_TILE) {
        int o = t0 + tid;
        if (o < LROW)
            out[rb + o] = sPrim[tid + 8] - 0.01f * (sf[tid + 1] - sf[tid]);
    }
}

// ---------------- launch ----------------
extern "C" void kernel_launch(void* const* d_in, const int* in_sizes, int n_in,
                              void* d_out, int out_size) {
    const float* Prim = (const float*)d_in[0];
    const float* W1   = (const float*)d_in[1];
    const float* b1   = (const float*)d_in[2];
    const float* W2   = (const float*)d_in[3];
    const float* b2   = (const float*)d_in[4];
    const float* W3   = (const float*)d_in[5];
    const float* b3   = (const float*)d_in[6];
    float* out = (float*)d_out;

    cudaFuncSetAttribute(k_mega, cudaFuncAttributeMaxDynamicSharedMemorySize, SMEM_TOTAL);

    k_pre<<<280, 1024>>>(Prim, W2, W3);
    k_mega<<<dim3(NTILES, NROWS), 256, SMEM_TOTAL>>>(Prim, W1, b1, b2, b3, out);
}